// round 1
// baseline (speedup 1.0000x reference)
#include <cuda_runtime.h>
#include <math.h>

// Problem constants: act is (4, 4096, 4096) fp32, GROUP_SIZE=32.
// Reduction over axes (0,1,3) -> 128 global group maxes along last dim.
#define DCOL   4096
#define NGROUP 128          // DCOL / 32
#define NROWS  16384        // 4 * 4096
#define NELEM  ((size_t)NROWS * (size_t)DCOL)   // 67,108,864
#define N4     (NELEM / 4)                      // 16,777,216 float4

// Scratch (allocation-free rule: __device__ globals)
__device__ unsigned int g_max_bits[NGROUP];
__device__ float        g_scale[NGROUP];
__device__ float        g_inv_scale[NGROUP];

// ---------------------------------------------------------------------------
// Phase 0: reset the atomic-max accumulators (graph replays must be
// deterministic, so state is re-initialized on every capture/replay).
// ---------------------------------------------------------------------------
__global__ void mx_init_kernel() {
    if (threadIdx.x < NGROUP) g_max_bits[threadIdx.x] = 0u;
}

// ---------------------------------------------------------------------------
// Phase 1: global abs-max per group. 1024 threads/block: thread x owns the
// float4 at column 4x of every row it visits -> group index is fixed (x>>3).
// Grid-stride over rows, single running max register per thread, 8-lane
// shuffle tree, 1 atomicMax per group per block (128/block).
// ---------------------------------------------------------------------------
__global__ void mx_reduce_kernel(const float4* __restrict__ act4) {
    const int x = threadIdx.x;                 // 0..1023 (one full row of float4)
    float m = 0.0f;
    for (int row = blockIdx.x; row < NROWS; row += gridDim.x) {
        float4 v = act4[(size_t)row * (DCOL / 4) + x];
        float a = fmaxf(fmaxf(fabsf(v.x), fabsf(v.y)),
                        fmaxf(fabsf(v.z), fabsf(v.w)));
        m = fmaxf(m, a);
    }
    // Reduce across the 8 lanes that share a group (lanes x..x+7, x%8==0 base)
    m = fmaxf(m, __shfl_xor_sync(0xffffffffu, m, 1));
    m = fmaxf(m, __shfl_xor_sync(0xffffffffu, m, 2));
    m = fmaxf(m, __shfl_xor_sync(0xffffffffu, m, 4));
    if ((x & 7) == 0) {
        // abs values are non-negative: float bit pattern order == uint order
        atomicMax(&g_max_bits[x >> 3], __float_as_uint(m));
    }
}

// ---------------------------------------------------------------------------
// Phase 2 (tiny): exps = floor(log2(max)) (ilogbf is exact for normals AND
// subnormals), scale = 2^exps. Writes the exps output tail and precomputes
// the exact power-of-two reciprocal for the quantize pass.
// ---------------------------------------------------------------------------
__global__ void mx_finalize_kernel(float* __restrict__ exps_out) {
    int g = threadIdx.x;
    if (g >= NGROUP) return;
    float mx = __uint_as_float(g_max_bits[g]);
    float e  = (mx > 0.0f) ? (float)ilogbf(mx) : 0.0f;
    float s  = exp2f(e);
    exps_out[g]    = e;
    g_scale[g]     = s;
    g_inv_scale[g] = 1.0f / s;   // exact (power of two)
}

// ---------------------------------------------------------------------------
// Phase 3: quantize. One float4 per thread, exact grid. All arithmetic is
// exact (pow2 scaling) and rintf == round-half-to-even == jnp.round.
// ---------------------------------------------------------------------------
__device__ __forceinline__ float mx_quant1(float a, float s, float inv) {
    float r = fminf(fabsf(a) * inv, 1.0f);     // clip(|a|/s, 0, 1), exact
    float m = rintf(r * 8.0f) * 0.125f;        // round-half-even mantissa
    return copysignf(s * m, a);                // exact reconstruct
}

__global__ void mx_quant_kernel(const float4* __restrict__ act4,
                                float4* __restrict__ out4) {
    size_t i = (size_t)blockIdx.x * blockDim.x + threadIdx.x;
    // column-of-float4 = i & 1023 (D/4 = 1024, pow2); group = col>>3
    int g = (int)(i & 1023u) >> 3;
    float s   = __ldg(&g_scale[g]);
    float inv = __ldg(&g_inv_scale[g]);
    float4 v = act4[i];
    float4 q;
    q.x = mx_quant1(v.x, s, inv);
    q.y = mx_quant1(v.y, s, inv);
    q.z = mx_quant1(v.z, s, inv);
    q.w = mx_quant1(v.w, s, inv);
    out4[i] = q;
}

// ---------------------------------------------------------------------------
// Launch: init -> reduce -> finalize -> quantize (stream-ordered, graph-safe)
// Output layout: q (67,108,864 floats) followed by exps (128 floats).
// ---------------------------------------------------------------------------
extern "C" void kernel_launch(void* const* d_in, const int* in_sizes, int n_in,
                              void* d_out, int out_size) {
    const float4* act4 = (const float4*)d_in[0];
    float* out      = (float*)d_out;
    // exps tail: robust to out_size being exactly NELEM + NGROUP
    float* exps_out = out + ((size_t)out_size - NGROUP);

    mx_init_kernel<<<1, 128>>>();
    mx_reduce_kernel<<<296, 1024>>>(act4);
    mx_finalize_kernel<<<1, 128>>>(exps_out);
    mx_quant_kernel<<<(unsigned)(N4 / 256), 256>>>(act4, (float4*)out);
}